// round 14
// baseline (speedup 1.0000x reference)
#include <cuda_runtime.h>
#include <cuda_fp16.h>
#include <cstdint>

#define BATCH 2
#define SEQ   2048
#define DIM   1024
#define HEADS 16
#define HDIM  64
#define MROWS (BATCH*SEQ)          // 4096
#define QKVN  (3*DIM)              // 3072
#define QSCL  (0.03125f * 1.44269504088896f)   // DIM^-0.5 * log2e (use ex2)

// ---------------- scratch (device globals; no allocation allowed) ----------
__device__ __half g_xh[MROWS*DIM];                 // x hi
__device__ __half g_wqkvTh[QKVN*DIM];              // [n][k] hi
__device__ __half g_woutTh[DIM*DIM];               // [n][k] hi
__device__ __half g_qh[BATCH*HEADS*SEQ*HDIM];      // q hi (pre-scaled)
__device__ __half g_kh[BATCH*HEADS*SEQ*HDIM];      // k hi
__device__ __half g_vh[BATCH*HEADS*SEQ*HDIM];      // v hi [bh][s][d]
__device__ __half g_aoh[MROWS*DIM];                // attn out hi

// ---------------- helpers ----------------------------------------------------
__device__ __forceinline__ uint32_t smem_u32(const void* p){
    uint32_t a;
    asm("{ .reg .u64 t; cvta.to.shared.u64 t, %1; cvt.u32.u64 %0, t; }"
        : "=r"(a) : "l"(p));
    return a;
}
__device__ __forceinline__ uint32_t swz128(uint32_t o){ return o ^ ((o>>3)&0x70u); }

__device__ __forceinline__ void cp16(uint32_t saddr, const void* gaddr){
    asm volatile("cp.async.cg.shared.global [%0], [%1], 16;" :: "r"(saddr), "l"(gaddr));
}
#define CP_COMMIT() asm volatile("cp.async.commit_group;" ::: "memory")
#define CP_WAIT0()  asm volatile("cp.async.wait_group 0;"  ::: "memory")
#define CP_WAIT1()  asm volatile("cp.async.wait_group 1;"  ::: "memory")

__device__ __forceinline__ void ldm4(uint32_t addr, uint32_t r[4]){
    asm volatile("ldmatrix.sync.aligned.m8n8.x4.shared.b16 {%0,%1,%2,%3}, [%4];"
                 : "=r"(r[0]),"=r"(r[1]),"=r"(r[2]),"=r"(r[3]) : "r"(addr));
}
__device__ __forceinline__ void ldm4t(uint32_t addr, uint32_t r[4]){
    asm volatile("ldmatrix.sync.aligned.m8n8.x4.trans.shared.b16 {%0,%1,%2,%3}, [%4];"
                 : "=r"(r[0]),"=r"(r[1]),"=r"(r[2]),"=r"(r[3]) : "r"(addr));
}
__device__ __forceinline__ void mma_f16(float d[4], const uint32_t a[4], const uint32_t b[2]){
    asm volatile("mma.sync.aligned.m16n8k16.row.col.f32.f16.f16.f32 "
        "{%0,%1,%2,%3}, {%4,%5,%6,%7}, {%8,%9}, {%0,%1,%2,%3};"
        : "+f"(d[0]),"+f"(d[1]),"+f"(d[2]),"+f"(d[3])
        : "r"(a[0]),"r"(a[1]),"r"(a[2]),"r"(a[3]), "r"(b[0]),"r"(b[1]));
}
// fp16-accumulated mma (double rate)
__device__ __forceinline__ void mma_f16a(uint32_t d[2], const uint32_t a[4], const uint32_t b[2]){
    asm volatile("mma.sync.aligned.m16n8k16.row.col.f16.f16.f16.f16 "
        "{%0,%1}, {%2,%3,%4,%5}, {%6,%7}, {%0,%1};"
        : "+r"(d[0]),"+r"(d[1])
        : "r"(a[0]),"r"(a[1]),"r"(a[2]),"r"(a[3]), "r"(b[0]),"r"(b[1]));
}
__device__ __forceinline__ uint32_t ex2_h2(uint32_t x){
    uint32_t r;
    asm("ex2.approx.f16x2 %0, %1;" : "=r"(r) : "r"(x));
    return r;
}

// ---------------- prep ---------------------------------------------------------
__global__ void conv_x_k(const float* __restrict__ in){
    int i = blockIdx.x*256 + threadIdx.x;           // float4 index
    float4 v = ((const float4*)in)[i];
    __half2* H = (__half2*)g_xh;
    H[2*i]   = __halves2half2(__float2half_rn(v.x), __float2half_rn(v.y));
    H[2*i+1] = __halves2half2(__float2half_rn(v.z), __float2half_rn(v.w));
}

// transpose fp32 [rows][cols] -> fp16 hi [cols][rows]
__device__ __forceinline__ void tr_hi(const float* __restrict__ in,
        __half* __restrict__ oh, int rows, int cols){
    __shared__ float t[32][33];
    int c0 = blockIdx.x * 32, r0 = blockIdx.y * 32;
    int x = threadIdx.x, y = threadIdx.y;
    #pragma unroll
    for (int i = 0; i < 32; i += 8) t[y+i][x] = in[(size_t)(r0+y+i)*cols + c0+x];
    __syncthreads();
    #pragma unroll
    for (int i = 0; i < 32; i += 8)
        oh[(size_t)(c0+y+i)*rows + r0+x] = __float2half_rn(t[x][y+i]);
}
__global__ void tr_wqkv_k(const float* __restrict__ w){ tr_hi(w, g_wqkvTh, DIM, QKVN); }
__global__ void tr_wout_k(const float* __restrict__ w){ tr_hi(w, g_woutTh, DIM, DIM); }

// ---------------- GEMM core: 4 warps, 64x64 warp tile, chunked fp16 acc --------
// C[128,128], 128 threads (4 warps: 2m x 2n). A,B hi-only k-major, 128B rows.
// K-chunk = 64: fp16 accumulation within chunk (double-rate HMMA), fp32 add
// across chunks. Per chunk processed in two n-halves so the live fp16
// accumulator block stays at 32 regs. 3 buffers, 1 barrier per chunk.
#define KC 64
#define NCHUNK (DIM/KC)
#define GBUF 32768u                 // 16K A + 16K B per buffer
#define GEMM_SMEM (3*GBUF)

__device__ __forceinline__ void g_issue(uint32_t sb, int buf,
        const __half* __restrict__ Ah, const __half* __restrict__ Bh,
        int c, int tid){
    uint32_t base = sb + (uint32_t)buf * GBUF;
    #pragma unroll
    for (int i = 0; i < 8; i++){
        int idx = tid + i*128;
        int row = idx >> 3, g = idx & 7;
        uint32_t off = swz128((uint32_t)(row*128 + g*16));
        cp16(base + off,          Ah + (size_t)row*DIM + c*KC + g*8);
        cp16(base + 16384u + off, Bh + (size_t)row*DIM + c*KC + g*8);
    }
    CP_COMMIT();
}

__device__ __forceinline__ void g_compute(uint32_t sb, int buf,
        int wm, int wn, int lane, float acc[4][8][4]){
    uint32_t abase = sb + (uint32_t)buf * GBUF;
    uint32_t bbase = abase + 16384u;
    int mat = lane >> 3;
    int rA  = (mat & 1)*8 + (lane & 7);
    int kgA = mat >> 1;
    int ntB = mat >> 1;
    int kgB = mat & 1;
    int rB  = lane & 7;
    #pragma unroll
    for (int nh = 0; nh < 2; nh++){                 // n-half: frags nh*4..nh*4+3
        uint32_t acc2[4][4][2];
        #pragma unroll
        for (int mi = 0; mi < 4; mi++)
            #pragma unroll
            for (int nj = 0; nj < 4; nj++){ acc2[mi][nj][0]=0u; acc2[mi][nj][1]=0u; }
        #pragma unroll
        for (int s = 0; s < 4; s++){
            uint32_t ah[4][4];
            #pragma unroll
            for (int mi = 0; mi < 4; mi++){
                uint32_t off = (uint32_t)((wm + mi*16 + rA)*128 + s*32 + kgA*16);
                ldm4(abase + swz128(off), ah[mi]);
            }
            uint32_t bh[2][4];
            #pragma unroll
            for (int p = 0; p < 2; p++){
                uint32_t off = (uint32_t)((wn + (nh*2+p)*16 + ntB*8 + rB)*128 + s*32 + kgB*16);
                ldm4(bbase + swz128(off), bh[p]);
            }
            #pragma unroll
            for (int mi = 0; mi < 4; mi++)
                #pragma unroll
                for (int nj = 0; nj < 4; nj++)
                    mma_f16a(acc2[mi][nj], ah[mi], &bh[nj>>1][(nj&1)*2]);
        }
        // fp32 combine (cross-chunk accumulation in fp32)
        #pragma unroll
        for (int mi = 0; mi < 4; mi++)
            #pragma unroll
            for (int nj = 0; nj < 4; nj++){
                float2 lo = __half22float2(*(__half2*)&acc2[mi][nj][0]);
                float2 hi = __half22float2(*(__half2*)&acc2[mi][nj][1]);
                acc[mi][nh*4+nj][0] += lo.x;
                acc[mi][nh*4+nj][1] += lo.y;
                acc[mi][nh*4+nj][2] += hi.x;
                acc[mi][nh*4+nj][3] += hi.y;
            }
    }
}

__device__ __forceinline__ void gemm_main(uint32_t sb,
        const __half* Ah, const __half* Bh,
        int tid, int wm, int wn, int lane, float acc[4][8][4]){
    g_issue(sb, 0, Ah, Bh, 0, tid);
    g_issue(sb, 1, Ah, Bh, 1, tid);
    int bc = 0, bn2 = 2;            // rotating buffer indices: c%3, (c+2)%3
    #pragma unroll 1
    for (int c = 0; c < NCHUNK; c++){
        if (c + 1 < NCHUNK) CP_WAIT1(); else CP_WAIT0();
        __syncthreads();
        if (c + 2 < NCHUNK)
            g_issue(sb, bn2, Ah, Bh, c+2, tid);
        g_compute(sb, bc, wm, wn, lane, acc);
        if (++bc == 3) bc = 0;
        if (++bn2 == 3) bn2 = 0;
    }
}

__global__ void __launch_bounds__(128,2) gemm_qkv_tc(){
    extern __shared__ char smem[];
    uint32_t sb = smem_u32(smem);
    int tid = threadIdx.x, lane = tid & 31, wid = tid >> 5;
    int wm = (wid & 1)*64, wn = (wid >> 1)*64;
    int bm = blockIdx.y*128, bn = blockIdx.x*128;

    float acc[4][8][4];
    #pragma unroll
    for (int i=0;i<4;i++) for(int j=0;j<8;j++) for(int r=0;r<4;r++) acc[i][j][r]=0.f;

    gemm_main(sb, g_xh + (size_t)bm*DIM, g_wqkvTh + (size_t)bn*DIM,
              tid, wm, wn, lane, acc);

    // epilogue: scatter into q (pre-scaled), k, v — all fp16 hi
    int cb = bn + wn;                 // 64-aligned
    int part = cb >> 10;
    int h = (cb & (DIM-1)) >> 6;
    __half* dstp = (part==0 ? g_qh : (part==1 ? g_kh : g_vh));
    float scl = (part==0) ? QSCL : 1.0f;
    #pragma unroll
    for (int mi = 0; mi < 4; mi++){
        #pragma unroll
        for (int hi2 = 0; hi2 < 2; hi2++){
            int m = bm + wm + mi*16 + hi2*8 + (lane>>2);
            int b = m >> 11, n = m & (SEQ-1);
            size_t base = ((size_t)(b*HEADS + h)*SEQ + n)*HDIM + (lane&3)*2;
            #pragma unroll
            for (int nj = 0; nj < 8; nj++){
                float v0 = acc[mi][nj][hi2*2]*scl, v1 = acc[mi][nj][hi2*2+1]*scl;
                *(__half2*)(dstp + base + nj*8) =
                    __halves2half2(__float2half_rn(v0), __float2half_rn(v1));
            }
        }
    }
}

__global__ void __launch_bounds__(128,2) gemm_out_tc(const float* __restrict__ bias,
                                                     float* __restrict__ Out){
    extern __shared__ char smem[];
    uint32_t sb = smem_u32(smem);
    int tid = threadIdx.x, lane = tid & 31, wid = tid >> 5;
    int wm = (wid & 1)*64, wn = (wid >> 1)*64;
    int bm = blockIdx.y*128, bn = blockIdx.x*128;

    float acc[4][8][4];
    #pragma unroll
    for (int i=0;i<4;i++) for(int j=0;j<8;j++) for(int r=0;r<4;r++) acc[i][j][r]=0.f;

    gemm_main(sb, g_aoh + (size_t)bm*DIM, g_woutTh + (size_t)bn*DIM,
              tid, wm, wn, lane, acc);

    #pragma unroll
    for (int mi = 0; mi < 4; mi++){
        #pragma unroll
        for (int hi2 = 0; hi2 < 2; hi2++){
            int m = bm + wm + mi*16 + hi2*8 + (lane>>2);
            float* dst = Out + (size_t)m*DIM + bn + wn + (lane&3)*2;
            #pragma unroll
            for (int nj = 0; nj < 8; nj++){
                int c = bn + wn + nj*8 + (lane&3)*2;
                float2 v = make_float2(acc[mi][nj][hi2*2]   + bias[c],
                                       acc[mi][nj][hi2*2+1] + bias[c+1]);
                *(float2*)(dst + nj*8) = v;
            }
        }
    }
}

// ---------------- flash attention: m32 warps, Q folded into K1, 3 CTA/SM ------
// (unchanged from R13)
#define AK0 0u
#define AK1 16384u
#define AQ  AK1
#define AV0 32768u
#define AV1 49152u
#define ATT_SMEM (AV1 + 16384u)     // 64K

__device__ __forceinline__ void attn_issue_tile(uint32_t sb, int buf,
        const __half* __restrict__ Kh, const __half* __restrict__ Vs,
        int t0, int tid){
    uint32_t kb = sb + (buf ? AK1 : AK0);
    uint32_t vb = sb + (buf ? AV1 : AV0);
    #pragma unroll
    for (int i = 0; i < 8; i++){
        int idx = tid + i*128;
        int row = idx >> 3, g = idx & 7;
        uint32_t off = swz128((uint32_t)(row*128 + g*16));
        cp16(kb + off, Kh + (size_t)(t0+row)*HDIM + g*8);
        cp16(vb + off, Vs + (size_t)(t0+row)*HDIM + g*8);
    }
    CP_COMMIT();
}

__global__ void __launch_bounds__(128,3) attn_tc(){
    extern __shared__ char smem[];
    uint32_t sb = smem_u32(smem);
    int tid = threadIdx.x, lane = tid & 31, wid = tid >> 5;
    int wm = wid * 32;                 // 4 warps x 32 rows = 128
    int b = blockIdx.z, h = blockIdx.y, bh = b*HEADS + h;
    int qbase = blockIdx.x * 128;

    const __half* Qh = g_qh + ((size_t)bh*SEQ + qbase)*HDIM;
    const __half* Kh = g_kh + (size_t)bh*SEQ*HDIM;
    const __half* Vs = g_vh + (size_t)bh*SEQ*HDIM;

    // Q tile into AQ (= K1 buffer) — own cp.async group, consumed at t=0 only
    #pragma unroll
    for (int i = 0; i < 8; i++){
        int idx = tid + i*128;
        int row = idx >> 3, g = idx & 7;
        cp16(sb + AQ + swz128((uint32_t)(row*128 + g*16)),
             Qh + (size_t)row*HDIM + g*8);
    }
    CP_COMMIT();

    attn_issue_tile(sb, 0, Kh, Vs, 0, tid);

    float oacc[2][8][4];               // [msub][n-frag][reg], d 0..63
    float oaccl[2][4];                 // [msub][reg], ones column (row sums)
    #pragma unroll
    for (int m = 0; m < 2; m++){
        #pragma unroll
        for (int j = 0; j < 8; j++)
            #pragma unroll
            for (int r = 0; r < 4; r++) oacc[m][j][r] = 0.f;
        #pragma unroll
        for (int r = 0; r < 4; r++) oaccl[m][r] = 0.f;
    }

    int mat = lane >> 3;
    int rA  = (mat & 1)*8 + (lane & 7);
    int kgA = mat >> 1;
    int ntB = mat >> 1;
    int kgB = mat & 1;
    int rB  = lane & 7;
    int kvrow = (lane & 7) + ((lane >> 3) & 1) * 8;
    int kvchk = (lane >> 4);
    uint32_t bvc = ((lane >> 2) == 0) ? 0x3C003C00u : 0u;
    uint32_t bvc2[2] = { bvc, bvc };

    uint32_t qfrag[2][4][4];           // [msub][s][reg], loaded once at t=0

    #pragma unroll 1
    for (int t = 0; t < 16; t++){
        uint32_t kb = sb + ((t & 1) ? AK1 : AK0);
        uint32_t vb = sb + ((t & 1) ? AV1 : AV0);
        CP_WAIT0();
        __syncthreads();               // also protects buffers from next issue

        if (t == 0){
            #pragma unroll
            for (int m = 0; m < 2; m++)
                #pragma unroll
                for (int s = 0; s < 4; s++){
                    uint32_t off = (uint32_t)((wm + m*16 + rA)*128 + s*32 + kgA*16);
                    ldm4(sb + AQ + swz128(off), qfrag[m][s]);
                }
            __syncthreads();           // qfrag read before K1 overwrite below
        }
        if (t + 1 < 16)
            attn_issue_tile(sb, (t+1)&1, Kh, Vs, (t+1)*128, tid);

        // process key-tile in two 64-key halves to bound live registers
        #pragma unroll
        for (int half = 0; half < 2; half++){
            // ---- S = Q @ K^T : m32 x n64, k=64, fp16 accumulators ----
            uint32_t sacc2[2][16];
            #pragma unroll
            for (int m = 0; m < 2; m++)
                #pragma unroll
                for (int j = 0; j < 16; j++) sacc2[m][j] = 0u;
            #pragma unroll
            for (int s = 0; s < 4; s++){
                #pragma unroll
                for (int p = 0; p < 4; p++){
                    uint32_t bk[4];
                    uint32_t off = (uint32_t)(((half*4 + p)*16 + ntB*8 + rB)*128
                                              + s*32 + kgB*16);
                    ldm4(kb + swz128(off), bk);
                    #pragma unroll
                    for (int m = 0; m < 2; m++){
                        mma_f16a(&sacc2[m][4*p],   qfrag[m][s], &bk[0]);
                        mma_f16a(&sacc2[m][4*p+2], qfrag[m][s], &bk[2]);
                    }
                }
            }

            // ---- P = 2^S in place ----
            #pragma unroll
            for (int m = 0; m < 2; m++)
                #pragma unroll
                for (int j = 0; j < 16; j++) sacc2[m][j] = ex2_h2(sacc2[m][j]);

            // ---- O += P @ V (64 keys): V via ldmatrix.trans; ones via const --
            #pragma unroll
            for (int ks = 0; ks < 4; ks++){
                int krow0 = half*64 + ks*16;
                #pragma unroll
                for (int p = 0; p < 4; p++){
                    uint32_t bv[4];
                    uint32_t off = (uint32_t)((krow0 + kvrow)*128 + (p*2 + kvchk)*16);
                    ldm4t(vb + swz128(off), bv);
                    #pragma unroll
                    for (int m = 0; m < 2; m++){
                        mma_f16(oacc[m][2*p],   &sacc2[m][4*ks], &bv[0]);
                        mma_f16(oacc[m][2*p+1], &sacc2[m][4*ks], &bv[2]);
                    }
                }
                #pragma unroll
                for (int m = 0; m < 2; m++)
                    mma_f16(oaccl[m], &sacc2[m][4*ks], bvc2);
            }
        }
    }

    // ---- normalize by l (ones fragment col 0) and write ----
    #pragma unroll
    for (int m = 0; m < 2; m++){
        float l0 = __shfl_sync(0xffffffffu, oaccl[m][0], lane & ~3);
        float l1 = __shfl_sync(0xffffffffu, oaccl[m][2], lane & ~3);
        float inv0 = 1.0f / l0, inv1 = 1.0f / l1;
        int r0 = qbase + wm + m*16 + (lane >> 2);
        size_t base0 = ((size_t)(b*SEQ) + r0)*DIM     + h*HDIM + (lane&3)*2;
        size_t base1 = ((size_t)(b*SEQ) + r0 + 8)*DIM + h*HDIM + (lane&3)*2;
        #pragma unroll
        for (int f = 0; f < 8; f++){
            *(__half2*)(g_aoh + base0 + f*8) =
                __halves2half2(__float2half_rn(oacc[m][f][0]*inv0),
                               __float2half_rn(oacc[m][f][1]*inv0));
            *(__half2*)(g_aoh + base1 + f*8) =
                __halves2half2(__float2half_rn(oacc[m][f][2]*inv1),
                               __float2half_rn(oacc[m][f][3]*inv1));
        }
    }
}

// ---------------- launch -----------------------------------------------------
extern "C" void kernel_launch(void* const* d_in, const int* in_sizes, int n_in,
                              void* d_out, int out_size){
    const float* x     = (const float*)d_in[0];
    const float* w_qkv = (const float*)d_in[1];
    const float* w_out = (const float*)d_in[2];
    const float* b_out = (const float*)d_in[3];
    float* out = (float*)d_out;

    cudaFuncSetAttribute(gemm_qkv_tc, cudaFuncAttributeMaxDynamicSharedMemorySize, GEMM_SMEM);
    cudaFuncSetAttribute(gemm_out_tc, cudaFuncAttributeMaxDynamicSharedMemorySize, GEMM_SMEM);
    cudaFuncSetAttribute(attn_tc,     cudaFuncAttributeMaxDynamicSharedMemorySize, ATT_SMEM);

    dim3 tb(32, 8);
    conv_x_k<<<MROWS*DIM/4/256, 256>>>(x);
    tr_wqkv_k<<<dim3(QKVN/32, DIM/32), tb>>>(w_qkv);
    tr_wout_k<<<dim3(DIM/32,  DIM/32), tb>>>(w_out);

    gemm_qkv_tc<<<dim3(QKVN/128, MROWS/128), 128, GEMM_SMEM>>>();

    attn_tc<<<dim3(SEQ/128, HEADS, BATCH), 128, ATT_SMEM>>>();

    gemm_out_tc<<<dim3(DIM/128, MROWS/128), 128, GEMM_SMEM>>>(b_out, out);
}

// round 15
// speedup vs baseline: 1.0679x; 1.0679x over previous
#include <cuda_runtime.h>
#include <cuda_fp16.h>
#include <cstdint>

#define BATCH 2
#define SEQ   2048
#define DIM   1024
#define HEADS 16
#define HDIM  64
#define MROWS (BATCH*SEQ)          // 4096
#define QKVN  (3*DIM)              // 3072
#define QSCL  (0.03125f * 1.44269504088896f)   // DIM^-0.5 * log2e (use ex2)

// ---------------- scratch (device globals; no allocation allowed) ----------
__device__ __half g_xh[MROWS*DIM];                 // x hi
__device__ __half g_wqkvTh[QKVN*DIM];              // [n][k] hi
__device__ __half g_woutTh[DIM*DIM];               // [n][k] hi
__device__ __half g_qh[BATCH*HEADS*SEQ*HDIM];      // q hi (pre-scaled)
__device__ __half g_kh[BATCH*HEADS*SEQ*HDIM];      // k hi
__device__ __half g_vh[BATCH*HEADS*SEQ*HDIM];      // v hi [bh][s][d]
__device__ __half g_aoh[MROWS*DIM];                // attn out hi

// ---------------- helpers ----------------------------------------------------
__device__ __forceinline__ uint32_t smem_u32(const void* p){
    uint32_t a;
    asm("{ .reg .u64 t; cvta.to.shared.u64 t, %1; cvt.u32.u64 %0, t; }"
        : "=r"(a) : "l"(p));
    return a;
}
__device__ __forceinline__ uint32_t swz128(uint32_t o){ return o ^ ((o>>3)&0x70u); }

__device__ __forceinline__ void cp16(uint32_t saddr, const void* gaddr){
    asm volatile("cp.async.cg.shared.global [%0], [%1], 16;" :: "r"(saddr), "l"(gaddr));
}
#define CP_COMMIT() asm volatile("cp.async.commit_group;" ::: "memory")
#define CP_WAIT0()  asm volatile("cp.async.wait_group 0;"  ::: "memory")
#define CP_WAIT1()  asm volatile("cp.async.wait_group 1;"  ::: "memory")

__device__ __forceinline__ void ldm4(uint32_t addr, uint32_t r[4]){
    asm volatile("ldmatrix.sync.aligned.m8n8.x4.shared.b16 {%0,%1,%2,%3}, [%4];"
                 : "=r"(r[0]),"=r"(r[1]),"=r"(r[2]),"=r"(r[3]) : "r"(addr));
}
__device__ __forceinline__ void ldm4t(uint32_t addr, uint32_t r[4]){
    asm volatile("ldmatrix.sync.aligned.m8n8.x4.trans.shared.b16 {%0,%1,%2,%3}, [%4];"
                 : "=r"(r[0]),"=r"(r[1]),"=r"(r[2]),"=r"(r[3]) : "r"(addr));
}
__device__ __forceinline__ void mma_f16(float d[4], const uint32_t a[4], const uint32_t b[2]){
    asm volatile("mma.sync.aligned.m16n8k16.row.col.f32.f16.f16.f32 "
        "{%0,%1,%2,%3}, {%4,%5,%6,%7}, {%8,%9}, {%0,%1,%2,%3};"
        : "+f"(d[0]),"+f"(d[1]),"+f"(d[2]),"+f"(d[3])
        : "r"(a[0]),"r"(a[1]),"r"(a[2]),"r"(a[3]), "r"(b[0]),"r"(b[1]));
}
// fp16-accumulated mma (S-GEMM only; result feeds ex2 directly)
__device__ __forceinline__ void mma_f16a(uint32_t d[2], const uint32_t a[4], const uint32_t b[2]){
    asm volatile("mma.sync.aligned.m16n8k16.row.col.f16.f16.f16.f16 "
        "{%0,%1}, {%2,%3,%4,%5}, {%6,%7}, {%0,%1};"
        : "+r"(d[0]),"+r"(d[1])
        : "r"(a[0]),"r"(a[1]),"r"(a[2]),"r"(a[3]), "r"(b[0]),"r"(b[1]));
}
__device__ __forceinline__ uint32_t ex2_h2(uint32_t x){
    uint32_t r;
    asm("ex2.approx.f16x2 %0, %1;" : "=r"(r) : "r"(x));
    return r;
}

// ---------------- prep ---------------------------------------------------------
__global__ void conv_x_k(const float* __restrict__ in){
    int i = blockIdx.x*256 + threadIdx.x;           // float4 index
    float4 v = ((const float4*)in)[i];
    __half2* H = (__half2*)g_xh;
    H[2*i]   = __halves2half2(__float2half_rn(v.x), __float2half_rn(v.y));
    H[2*i+1] = __halves2half2(__float2half_rn(v.z), __float2half_rn(v.w));
}

// fused weight transposes: blocks x<96 -> w_qkv, else -> w_out
__global__ void tr_w_k(const float* __restrict__ wqkv, const float* __restrict__ wout){
    __shared__ float t[32][33];
    int bx = blockIdx.x;
    const float* in; __half* oh; int cols, c0;
    if (bx < QKVN/32){ in = wqkv; oh = g_wqkvTh; cols = QKVN; c0 = bx*32; }
    else             { in = wout; oh = g_woutTh; cols = DIM;  c0 = (bx - QKVN/32)*32; }
    int r0 = blockIdx.y * 32;
    int x = threadIdx.x, y = threadIdx.y;
    #pragma unroll
    for (int i = 0; i < 32; i += 8) t[y+i][x] = in[(size_t)(r0+y+i)*cols + c0+x];
    __syncthreads();
    #pragma unroll
    for (int i = 0; i < 32; i += 8)
        oh[(size_t)(c0+y+i)*DIM + r0+x] = __float2half_rn(t[x][y+i]);
}

// ---------------- fp16 mma GEMM core: 4 warps, 64x64 warp tile (R13) -----------
#define KC 64
#define NCHUNK (DIM/KC)
#define GBUF 32768u                 // 16K A + 16K B per buffer
#define GEMM_SMEM (3*GBUF)

__device__ __forceinline__ void g_issue(uint32_t sb, int buf,
        const __half* __restrict__ Ah, const __half* __restrict__ Bh,
        int c, int tid){
    uint32_t base = sb + (uint32_t)buf * GBUF;
    #pragma unroll
    for (int i = 0; i < 8; i++){
        int idx = tid + i*128;
        int row = idx >> 3, g = idx & 7;
        uint32_t off = swz128((uint32_t)(row*128 + g*16));
        cp16(base + off,          Ah + (size_t)row*DIM + c*KC + g*8);
        cp16(base + 16384u + off, Bh + (size_t)row*DIM + c*KC + g*8);
    }
    CP_COMMIT();
}

__device__ __forceinline__ void g_compute(uint32_t sb, int buf,
        int wm, int wn, int lane, float acc[4][8][4]){
    uint32_t abase = sb + (uint32_t)buf * GBUF;
    uint32_t bbase = abase + 16384u;
    int mat = lane >> 3;
    int rA  = (mat & 1)*8 + (lane & 7);
    int kgA = mat >> 1;
    int ntB = mat >> 1;
    int kgB = mat & 1;
    int rB  = lane & 7;
    #pragma unroll
    for (int s = 0; s < 4; s++){
        uint32_t ah[4][4];
        #pragma unroll
        for (int mi = 0; mi < 4; mi++){
            uint32_t off = (uint32_t)((wm + mi*16 + rA)*128 + s*32 + kgA*16);
            ldm4(abase + swz128(off), ah[mi]);
        }
        uint32_t bh[4][4];
        #pragma unroll
        for (int p = 0; p < 4; p++){
            uint32_t off = (uint32_t)((wn + p*16 + ntB*8 + rB)*128 + s*32 + kgB*16);
            ldm4(bbase + swz128(off), bh[p]);
        }
        #pragma unroll
        for (int mi = 0; mi < 4; mi++)
            #pragma unroll
            for (int nj = 0; nj < 8; nj++)
                mma_f16(acc[mi][nj], ah[mi], &bh[nj>>1][(nj&1)*2]);
    }
}

__device__ __forceinline__ void gemm_main(uint32_t sb,
        const __half* Ah, const __half* Bh,
        int tid, int wm, int wn, int lane, float acc[4][8][4]){
    g_issue(sb, 0, Ah, Bh, 0, tid);
    g_issue(sb, 1, Ah, Bh, 1, tid);
    int bc = 0, bn2 = 2;            // rotating buffer indices: c%3, (c+2)%3
    #pragma unroll 1
    for (int c = 0; c < NCHUNK; c++){
        if (c + 1 < NCHUNK) CP_WAIT1(); else CP_WAIT0();
        __syncthreads();
        if (c + 2 < NCHUNK)
            g_issue(sb, bn2, Ah, Bh, c+2, tid);
        g_compute(sb, bc, wm, wn, lane, acc);
        if (++bc == 3) bc = 0;
        if (++bn2 == 3) bn2 = 0;
    }
}

__global__ void __launch_bounds__(128,2) gemm_qkv_tc(){
    extern __shared__ char smem[];
    uint32_t sb = smem_u32(smem);
    int tid = threadIdx.x, lane = tid & 31, wid = tid >> 5;
    int wm = (wid & 1)*64, wn = (wid >> 1)*64;
    int bm = blockIdx.y*128, bn = blockIdx.x*128;

    float acc[4][8][4];
    #pragma unroll
    for (int i=0;i<4;i++) for(int j=0;j<8;j++) for(int r=0;r<4;r++) acc[i][j][r]=0.f;

    gemm_main(sb, g_xh + (size_t)bm*DIM, g_wqkvTh + (size_t)bn*DIM,
              tid, wm, wn, lane, acc);

    // epilogue: scatter into q (pre-scaled), k, v — all fp16 hi
    int cb = bn + wn;                 // 64-aligned
    int part = cb >> 10;
    int h = (cb & (DIM-1)) >> 6;
    __half* dstp = (part==0 ? g_qh : (part==1 ? g_kh : g_vh));
    float scl = (part==0) ? QSCL : 1.0f;
    #pragma unroll
    for (int mi = 0; mi < 4; mi++){
        #pragma unroll
        for (int hi2 = 0; hi2 < 2; hi2++){
            int m = bm + wm + mi*16 + hi2*8 + (lane>>2);
            int b = m >> 11, n = m & (SEQ-1);
            size_t base = ((size_t)(b*HEADS + h)*SEQ + n)*HDIM + (lane&3)*2;
            #pragma unroll
            for (int nj = 0; nj < 8; nj++){
                float v0 = acc[mi][nj][hi2*2]*scl, v1 = acc[mi][nj][hi2*2+1]*scl;
                *(__half2*)(dstp + base + nj*8) =
                    __halves2half2(__float2half_rn(v0), __float2half_rn(v1));
            }
        }
    }
}

__global__ void __launch_bounds__(128,2) gemm_out_tc(const float* __restrict__ bias,
                                                     float* __restrict__ Out){
    extern __shared__ char smem[];
    uint32_t sb = smem_u32(smem);
    int tid = threadIdx.x, lane = tid & 31, wid = tid >> 5;
    int wm = (wid & 1)*64, wn = (wid >> 1)*64;
    int bm = blockIdx.y*128, bn = blockIdx.x*128;

    float acc[4][8][4];
    #pragma unroll
    for (int i=0;i<4;i++) for(int j=0;j<8;j++) for(int r=0;r<4;r++) acc[i][j][r]=0.f;

    gemm_main(sb, g_aoh + (size_t)bm*DIM, g_woutTh + (size_t)bn*DIM,
              tid, wm, wn, lane, acc);

    #pragma unroll
    for (int mi = 0; mi < 4; mi++){
        #pragma unroll
        for (int hi2 = 0; hi2 < 2; hi2++){
            int m = bm + wm + mi*16 + hi2*8 + (lane>>2);
            float* dst = Out + (size_t)m*DIM + bn + wn + (lane&3)*2;
            #pragma unroll
            for (int nj = 0; nj < 8; nj++){
                int c = bn + wn + nj*8 + (lane&3)*2;
                float2 v = make_float2(acc[mi][nj][hi2*2]   + bias[c],
                                       acc[mi][nj][hi2*2+1] + bias[c+1]);
                *(float2*)(dst + nj*8) = v;
            }
        }
    }
}

// ---------------- flash attention: 64-key tiles, 4 CTA/SM single wave ---------
// CTA: (b, h, 128 queries). 128 threads / 4 warps, warp tile m32 x n64.
// smem: Q 16K resident | K0 8K | V0 8K | K1 8K | V1 8K = 48K -> 4 CTAs/SM.
// 32 key-tiles of 64 keys, double buffered. Q fragments re-loaded from smem
// per s-step (JIT) to stay under the 128-reg cap.
#define AQ  0u
#define AK0 16384u
#define AV0 24576u
#define AK1 32768u
#define AV1 40960u
#define ATT_SMEM 49152u

__device__ __forceinline__ void attn_issue_tile(uint32_t sb, int buf,
        const __half* __restrict__ Kh, const __half* __restrict__ Vs,
        int t0, int tid){
    uint32_t kb = sb + (buf ? AK1 : AK0);
    uint32_t vb = sb + (buf ? AV1 : AV0);
    #pragma unroll
    for (int i = 0; i < 4; i++){
        int idx = tid + i*128;
        int row = idx >> 3, g = idx & 7;       // row 0..63
        uint32_t off = swz128((uint32_t)(row*128 + g*16));
        cp16(kb + off, Kh + (size_t)(t0+row)*HDIM + g*8);
        cp16(vb + off, Vs + (size_t)(t0+row)*HDIM + g*8);
    }
    CP_COMMIT();
}

__global__ void __launch_bounds__(128,4) attn_tc(){
    extern __shared__ char smem[];
    uint32_t sb = smem_u32(smem);
    int tid = threadIdx.x, lane = tid & 31, wid = tid >> 5;
    int wm = wid * 32;                 // 4 warps x 32 rows = 128
    int b = blockIdx.z, h = blockIdx.y, bh = b*HEADS + h;
    int qbase = blockIdx.x * 128;

    const __half* Qh = g_qh + ((size_t)bh*SEQ + qbase)*HDIM;
    const __half* Kh = g_kh + (size_t)bh*SEQ*HDIM;
    const __half* Vs = g_vh + (size_t)bh*SEQ*HDIM;

    // Q tile resident in smem (128 rows x 128B), own cp.async group
    #pragma unroll
    for (int i = 0; i < 8; i++){
        int idx = tid + i*128;
        int row = idx >> 3, g = idx & 7;
        cp16(sb + AQ + swz128((uint32_t)(row*128 + g*16)),
             Qh + (size_t)row*HDIM + g*8);
    }
    CP_COMMIT();

    attn_issue_tile(sb, 0, Kh, Vs, 0, tid);

    float oacc[2][8][4];               // [msub][n-frag][reg], d 0..63
    float oaccl[2][4];                 // [msub][reg], ones column (row sums)
    #pragma unroll
    for (int m = 0; m < 2; m++){
        #pragma unroll
        for (int j = 0; j < 8; j++)
            #pragma unroll
            for (int r = 0; r < 4; r++) oacc[m][j][r] = 0.f;
        #pragma unroll
        for (int r = 0; r < 4; r++) oaccl[m][r] = 0.f;
    }

    int mat = lane >> 3;
    int rA  = (mat & 1)*8 + (lane & 7);
    int kgA = mat >> 1;
    int ntB = mat >> 1;
    int kgB = mat & 1;
    int rB  = lane & 7;
    int kvrow = (lane & 7) + ((lane >> 3) & 1) * 8;
    int kvchk = (lane >> 4);
    uint32_t bvc = ((lane >> 2) == 0) ? 0x3C003C00u : 0u;
    uint32_t bvc2[2] = { bvc, bvc };

    #pragma unroll 1
    for (int t = 0; t < 32; t++){
        uint32_t kb = sb + ((t & 1) ? AK1 : AK0);
        uint32_t vb = sb + ((t & 1) ? AV1 : AV0);
        CP_WAIT0();
        __syncthreads();               // also protects buffers from next issue
        if (t + 1 < 32)
            attn_issue_tile(sb, (t+1)&1, Kh, Vs, (t+1)*64, tid);

        // ---- S = Q @ K^T : m32 x n64, k=64, fp16 acc; Q frags JIT from smem
        uint32_t sacc2[2][16];
        #pragma unroll
        for (int m = 0; m < 2; m++)
            #pragma unroll
            for (int j = 0; j < 16; j++) sacc2[m][j] = 0u;
        #pragma unroll
        for (int s = 0; s < 4; s++){
            uint32_t qf[2][4];
            #pragma unroll
            for (int m = 0; m < 2; m++){
                uint32_t off = (uint32_t)((wm + m*16 + rA)*128 + s*32 + kgA*16);
                ldm4(sb + AQ + swz128(off), qf[m]);
            }
            #pragma unroll
            for (int p = 0; p < 4; p++){
                uint32_t bk[4];
                uint32_t off = (uint32_t)((p*16 + ntB*8 + rB)*128 + s*32 + kgB*16);
                ldm4(kb + swz128(off), bk);
                #pragma unroll
                for (int m = 0; m < 2; m++){
                    mma_f16a(&sacc2[m][4*p],   qf[m], &bk[0]);
                    mma_f16a(&sacc2[m][4*p+2], qf[m], &bk[2]);
                }
            }
        }

        // ---- P = 2^S in place ----
        #pragma unroll
        for (int m = 0; m < 2; m++)
            #pragma unroll
            for (int j = 0; j < 16; j++) sacc2[m][j] = ex2_h2(sacc2[m][j]);

        // ---- O += P @ V (64 keys): V via ldmatrix.trans; ones via const ----
        #pragma unroll
        for (int ks = 0; ks < 4; ks++){
            #pragma unroll
            for (int p = 0; p < 4; p++){
                uint32_t bv[4];
                uint32_t off = (uint32_t)((ks*16 + kvrow)*128 + (p*2 + kvchk)*16);
                ldm4t(vb + swz128(off), bv);
                #pragma unroll
                for (int m = 0; m < 2; m++){
                    mma_f16(oacc[m][2*p],   &sacc2[m][4*ks], &bv[0]);
                    mma_f16(oacc[m][2*p+1], &sacc2[m][4*ks], &bv[2]);
                }
            }
            #pragma unroll
            for (int m = 0; m < 2; m++)
                mma_f16(oaccl[m], &sacc2[m][4*ks], bvc2);
        }
    }

    // ---- normalize by l (ones fragment col 0) and write ----
    #pragma unroll
    for (int m = 0; m < 2; m++){
        float l0 = __shfl_sync(0xffffffffu, oaccl[m][0], lane & ~3);
        float l1 = __shfl_sync(0xffffffffu, oaccl[m][2], lane & ~3);
        float inv0 = 1.0f / l0, inv1 = 1.0f / l1;
        int r0 = qbase + wm + m*16 + (lane >> 2);
        size_t base0 = ((size_t)(b*SEQ) + r0)*DIM     + h*HDIM + (lane&3)*2;
        size_t base1 = ((size_t)(b*SEQ) + r0 + 8)*DIM + h*HDIM + (lane&3)*2;
        #pragma unroll
        for (int f = 0; f < 8; f++){
            *(__half2*)(g_aoh + base0 + f*8) =
                __halves2half2(__float2half_rn(oacc[m][f][0]*inv0),
                               __float2half_rn(oacc[m][f][1]*inv0));
            *(__half2*)(g_aoh + base1 + f*8) =
                __halves2half2(__float2half_rn(oacc[m][f][2]*inv1),
                               __float2half_rn(oacc[m][f][3]*inv1));
        }
    }
}

// ---------------- launch -----------------------------------------------------
extern "C" void kernel_launch(void* const* d_in, const int* in_sizes, int n_in,
                              void* d_out, int out_size){
    const float* x     = (const float*)d_in[0];
    const float* w_qkv = (const float*)d_in[1];
    const float* w_out = (const float*)d_in[2];
    const float* b_out = (const float*)d_in[3];
    float* out = (float*)d_out;

    cudaFuncSetAttribute(gemm_qkv_tc, cudaFuncAttributeMaxDynamicSharedMemorySize, GEMM_SMEM);
    cudaFuncSetAttribute(gemm_out_tc, cudaFuncAttributeMaxDynamicSharedMemorySize, GEMM_SMEM);
    cudaFuncSetAttribute(attn_tc,     cudaFuncAttributeMaxDynamicSharedMemorySize, ATT_SMEM);

    dim3 tb(32, 8);
    conv_x_k<<<MROWS*DIM/4/256, 256>>>(x);
    tr_w_k<<<dim3((QKVN+DIM)/32, DIM/32), tb>>>(w_qkv, w_out);

    gemm_qkv_tc<<<dim3(QKVN/128, MROWS/128), 128, GEMM_SMEM>>>();

    attn_tc<<<dim3(SEQ/128, HEADS, BATCH), 128, ATT_SMEM>>>();

    gemm_out_tc<<<dim3(DIM/128, MROWS/128), 128, GEMM_SMEM>>>(b_out, out);
}

// round 16
// speedup vs baseline: 1.1236x; 1.0521x over previous
#include <cuda_runtime.h>
#include <cuda_fp16.h>
#include <cstdint>

#define BATCH 2
#define SEQ   2048
#define DIM   1024
#define HEADS 16
#define HDIM  64
#define MROWS (BATCH*SEQ)          // 4096
#define QKVN  (3*DIM)              // 3072
#define QSCL  (0.03125f * 1.44269504088896f)   // DIM^-0.5 * log2e (use ex2)

// ---------------- scratch (device globals; no allocation allowed) ----------
__device__ __half g_xh[MROWS*DIM];                 // x hi
__device__ __half g_wqkvTh[QKVN*DIM];              // [n][k] hi
__device__ __half g_woutTh[DIM*DIM];               // [n][k] hi
__device__ __half g_qh[BATCH*HEADS*SEQ*HDIM];      // q hi (pre-scaled)
__device__ __half g_kh[BATCH*HEADS*SEQ*HDIM];      // k hi
__device__ __half g_vh[BATCH*HEADS*SEQ*HDIM];      // v hi [bh][s][d]
__device__ __half g_aoh[MROWS*DIM];                // attn out hi

// ---------------- helpers ----------------------------------------------------
__device__ __forceinline__ uint32_t smem_u32(const void* p){
    uint32_t a;
    asm("{ .reg .u64 t; cvta.to.shared.u64 t, %1; cvt.u32.u64 %0, t; }"
        : "=r"(a) : "l"(p));
    return a;
}
__device__ __forceinline__ uint32_t swz128(uint32_t o){ return o ^ ((o>>3)&0x70u); }

__device__ __forceinline__ void cp16(uint32_t saddr, const void* gaddr){
    asm volatile("cp.async.cg.shared.global [%0], [%1], 16;" :: "r"(saddr), "l"(gaddr));
}
#define CP_COMMIT() asm volatile("cp.async.commit_group;" ::: "memory")
#define CP_WAIT0()  asm volatile("cp.async.wait_group 0;"  ::: "memory")
#define CP_WAIT1()  asm volatile("cp.async.wait_group 1;"  ::: "memory")

__device__ __forceinline__ void ldm4(uint32_t addr, uint32_t r[4]){
    asm volatile("ldmatrix.sync.aligned.m8n8.x4.shared.b16 {%0,%1,%2,%3}, [%4];"
                 : "=r"(r[0]),"=r"(r[1]),"=r"(r[2]),"=r"(r[3]) : "r"(addr));
}
__device__ __forceinline__ void ldm4t(uint32_t addr, uint32_t r[4]){
    asm volatile("ldmatrix.sync.aligned.m8n8.x4.trans.shared.b16 {%0,%1,%2,%3}, [%4];"
                 : "=r"(r[0]),"=r"(r[1]),"=r"(r[2]),"=r"(r[3]) : "r"(addr));
}
__device__ __forceinline__ void mma_f16(float d[4], const uint32_t a[4], const uint32_t b[2]){
    asm volatile("mma.sync.aligned.m16n8k16.row.col.f32.f16.f16.f32 "
        "{%0,%1,%2,%3}, {%4,%5,%6,%7}, {%8,%9}, {%0,%1,%2,%3};"
        : "+f"(d[0]),"+f"(d[1]),"+f"(d[2]),"+f"(d[3])
        : "r"(a[0]),"r"(a[1]),"r"(a[2]),"r"(a[3]), "r"(b[0]),"r"(b[1]));
}
// fp16-accumulated mma (S-GEMM only; result feeds ex2 directly)
__device__ __forceinline__ void mma_f16a(uint32_t d[2], const uint32_t a[4], const uint32_t b[2]){
    asm volatile("mma.sync.aligned.m16n8k16.row.col.f16.f16.f16.f16 "
        "{%0,%1}, {%2,%3,%4,%5}, {%6,%7}, {%0,%1};"
        : "+r"(d[0]),"+r"(d[1])
        : "r"(a[0]),"r"(a[1]),"r"(a[2]),"r"(a[3]), "r"(b[0]),"r"(b[1]));
}
__device__ __forceinline__ uint32_t ex2_h2(uint32_t x){
    uint32_t r;
    asm("ex2.approx.f16x2 %0, %1;" : "=r"(r) : "r"(x));
    return r;
}

// ---------------- prep ---------------------------------------------------------
__global__ void conv_x_k(const float* __restrict__ in){
    int i = blockIdx.x*256 + threadIdx.x;           // float4 index
    float4 v = ((const float4*)in)[i];
    __half2* H = (__half2*)g_xh;
    H[2*i]   = __halves2half2(__float2half_rn(v.x), __float2half_rn(v.y));
    H[2*i+1] = __halves2half2(__float2half_rn(v.z), __float2half_rn(v.w));
}

// fused weight transposes: blocks x<96 -> w_qkv, else -> w_out
__global__ void tr_w_k(const float* __restrict__ wqkv, const float* __restrict__ wout){
    __shared__ float t[32][33];
    int bx = blockIdx.x;
    const float* in; __half* oh; int cols, c0;
    if (bx < QKVN/32){ in = wqkv; oh = g_wqkvTh; cols = QKVN; c0 = bx*32; }
    else             { in = wout; oh = g_woutTh; cols = DIM;  c0 = (bx - QKVN/32)*32; }
    int r0 = blockIdx.y * 32;
    int x = threadIdx.x, y = threadIdx.y;
    #pragma unroll
    for (int i = 0; i < 32; i += 8) t[y+i][x] = in[(size_t)(r0+y+i)*cols + c0+x];
    __syncthreads();
    #pragma unroll
    for (int i = 0; i < 32; i += 8)
        oh[(size_t)(c0+y+i)*DIM + r0+x] = __float2half_rn(t[x][y+i]);
}

// ---------------- fp16 mma GEMM core: 4 warps, 64x64 warp tile (R13) -----------
#define KC 64
#define NCHUNK (DIM/KC)
#define GBUF 32768u                 // 16K A + 16K B per buffer
#define GEMM_SMEM (3*GBUF)

__device__ __forceinline__ void g_issue(uint32_t sb, int buf,
        const __half* __restrict__ Ah, const __half* __restrict__ Bh,
        int c, int tid){
    uint32_t base = sb + (uint32_t)buf * GBUF;
    #pragma unroll
    for (int i = 0; i < 8; i++){
        int idx = tid + i*128;
        int row = idx >> 3, g = idx & 7;
        uint32_t off = swz128((uint32_t)(row*128 + g*16));
        cp16(base + off,          Ah + (size_t)row*DIM + c*KC + g*8);
        cp16(base + 16384u + off, Bh + (size_t)row*DIM + c*KC + g*8);
    }
    CP_COMMIT();
}

__device__ __forceinline__ void g_compute(uint32_t sb, int buf,
        int wm, int wn, int lane, float acc[4][8][4]){
    uint32_t abase = sb + (uint32_t)buf * GBUF;
    uint32_t bbase = abase + 16384u;
    int mat = lane >> 3;
    int rA  = (mat & 1)*8 + (lane & 7);
    int kgA = mat >> 1;
    int ntB = mat >> 1;
    int kgB = mat & 1;
    int rB  = lane & 7;
    #pragma unroll
    for (int s = 0; s < 4; s++){
        uint32_t ah[4][4];
        #pragma unroll
        for (int mi = 0; mi < 4; mi++){
            uint32_t off = (uint32_t)((wm + mi*16 + rA)*128 + s*32 + kgA*16);
            ldm4(abase + swz128(off), ah[mi]);
        }
        uint32_t bh[4][4];
        #pragma unroll
        for (int p = 0; p < 4; p++){
            uint32_t off = (uint32_t)((wn + p*16 + ntB*8 + rB)*128 + s*32 + kgB*16);
            ldm4(bbase + swz128(off), bh[p]);
        }
        #pragma unroll
        for (int mi = 0; mi < 4; mi++)
            #pragma unroll
            for (int nj = 0; nj < 8; nj++)
                mma_f16(acc[mi][nj], ah[mi], &bh[nj>>1][(nj&1)*2]);
    }
}

__device__ __forceinline__ void gemm_main(uint32_t sb,
        const __half* Ah, const __half* Bh,
        int tid, int wm, int wn, int lane, float acc[4][8][4]){
    g_issue(sb, 0, Ah, Bh, 0, tid);
    g_issue(sb, 1, Ah, Bh, 1, tid);
    int bc = 0, bn2 = 2;            // rotating buffer indices: c%3, (c+2)%3
    #pragma unroll 1
    for (int c = 0; c < NCHUNK; c++){
        if (c + 1 < NCHUNK) CP_WAIT1(); else CP_WAIT0();
        __syncthreads();
        if (c + 2 < NCHUNK)
            g_issue(sb, bn2, Ah, Bh, c+2, tid);
        g_compute(sb, bc, wm, wn, lane, acc);
        if (++bc == 3) bc = 0;
        if (++bn2 == 3) bn2 = 0;
    }
}

__global__ void __launch_bounds__(128,2) gemm_qkv_tc(){
    extern __shared__ char smem[];
    uint32_t sb = smem_u32(smem);
    int tid = threadIdx.x, lane = tid & 31, wid = tid >> 5;
    int wm = (wid & 1)*64, wn = (wid >> 1)*64;
    int bm = blockIdx.y*128, bn = blockIdx.x*128;

    float acc[4][8][4];
    #pragma unroll
    for (int i=0;i<4;i++) for(int j=0;j<8;j++) for(int r=0;r<4;r++) acc[i][j][r]=0.f;

    gemm_main(sb, g_xh + (size_t)bm*DIM, g_wqkvTh + (size_t)bn*DIM,
              tid, wm, wn, lane, acc);

    // epilogue: scatter into q (pre-scaled), k, v — all fp16 hi
    int cb = bn + wn;                 // 64-aligned
    int part = cb >> 10;
    int h = (cb & (DIM-1)) >> 6;
    __half* dstp = (part==0 ? g_qh : (part==1 ? g_kh : g_vh));
    float scl = (part==0) ? QSCL : 1.0f;
    #pragma unroll
    for (int mi = 0; mi < 4; mi++){
        #pragma unroll
        for (int hi2 = 0; hi2 < 2; hi2++){
            int m = bm + wm + mi*16 + hi2*8 + (lane>>2);
            int b = m >> 11, n = m & (SEQ-1);
            size_t base = ((size_t)(b*HEADS + h)*SEQ + n)*HDIM + (lane&3)*2;
            #pragma unroll
            for (int nj = 0; nj < 8; nj++){
                float v0 = acc[mi][nj][hi2*2]*scl, v1 = acc[mi][nj][hi2*2+1]*scl;
                *(__half2*)(dstp + base + nj*8) =
                    __halves2half2(__float2half_rn(v0), __float2half_rn(v1));
            }
        }
    }
}

__global__ void __launch_bounds__(128,2) gemm_out_tc(const float* __restrict__ bias,
                                                     float* __restrict__ Out){
    extern __shared__ char smem[];
    uint32_t sb = smem_u32(smem);
    int tid = threadIdx.x, lane = tid & 31, wid = tid >> 5;
    int wm = (wid & 1)*64, wn = (wid >> 1)*64;
    int bm = blockIdx.y*128, bn = blockIdx.x*128;

    float acc[4][8][4];
    #pragma unroll
    for (int i=0;i<4;i++) for(int j=0;j<8;j++) for(int r=0;r<4;r++) acc[i][j][r]=0.f;

    gemm_main(sb, g_aoh + (size_t)bm*DIM, g_woutTh + (size_t)bn*DIM,
              tid, wm, wn, lane, acc);

    #pragma unroll
    for (int mi = 0; mi < 4; mi++){
        #pragma unroll
        for (int hi2 = 0; hi2 < 2; hi2++){
            int m = bm + wm + mi*16 + hi2*8 + (lane>>2);
            float* dst = Out + (size_t)m*DIM + bn + wn + (lane&3)*2;
            #pragma unroll
            for (int nj = 0; nj < 8; nj++){
                int c = bn + wn + nj*8 + (lane&3)*2;
                float2 v = make_float2(acc[mi][nj][hi2*2]   + bias[c],
                                       acc[mi][nj][hi2*2+1] + bias[c+1]);
                *(float2*)(dst + nj*8) = v;
            }
        }
    }
}

// ---------------- flash attention: R13 config + shuffle row-sums ---------------
// CTA: (b, h, 128 queries). 128 threads / 4 warps, warp tile m32 x n128.
// smem: K0 16K | K1 16K (= Q at t=0) | V0 16K | V1 16K = 64K, 3 CTAs/SM.
// Key-tile processed in two 64-key halves. Row sums via HADD2 trees + quad
// butterfly (no ones-column MMAs: 20% fewer PV tensor cycles).
#define AK0 0u
#define AK1 16384u
#define AQ  AK1
#define AV0 32768u
#define AV1 49152u
#define ATT_SMEM (AV1 + 16384u)     // 64K

__device__ __forceinline__ void attn_issue_tile(uint32_t sb, int buf,
        const __half* __restrict__ Kh, const __half* __restrict__ Vs,
        int t0, int tid){
    uint32_t kb = sb + (buf ? AK1 : AK0);
    uint32_t vb = sb + (buf ? AV1 : AV0);
    #pragma unroll
    for (int i = 0; i < 8; i++){
        int idx = tid + i*128;
        int row = idx >> 3, g = idx & 7;
        uint32_t off = swz128((uint32_t)(row*128 + g*16));
        cp16(kb + off, Kh + (size_t)(t0+row)*HDIM + g*8);
        cp16(vb + off, Vs + (size_t)(t0+row)*HDIM + g*8);
    }
    CP_COMMIT();
}

__global__ void __launch_bounds__(128,3) attn_tc(){
    extern __shared__ char smem[];
    uint32_t sb = smem_u32(smem);
    int tid = threadIdx.x, lane = tid & 31, wid = tid >> 5;
    int wm = wid * 32;                 // 4 warps x 32 rows = 128
    int b = blockIdx.z, h = blockIdx.y, bh = b*HEADS + h;
    int qbase = blockIdx.x * 128;

    const __half* Qh = g_qh + ((size_t)bh*SEQ + qbase)*HDIM;
    const __half* Kh = g_kh + (size_t)bh*SEQ*HDIM;
    const __half* Vs = g_vh + (size_t)bh*SEQ*HDIM;

    // Q tile into AQ (= K1 buffer) — own cp.async group, consumed at t=0 only
    #pragma unroll
    for (int i = 0; i < 8; i++){
        int idx = tid + i*128;
        int row = idx >> 3, g = idx & 7;
        cp16(sb + AQ + swz128((uint32_t)(row*128 + g*16)),
             Qh + (size_t)row*HDIM + g*8);
    }
    CP_COMMIT();

    attn_issue_tile(sb, 0, Kh, Vs, 0, tid);

    float oacc[2][8][4];               // [msub][n-frag][reg], d 0..63
    float lsum[2][2];                  // [msub][row r / row r+8]
    #pragma unroll
    for (int m = 0; m < 2; m++){
        #pragma unroll
        for (int j = 0; j < 8; j++)
            #pragma unroll
            for (int r = 0; r < 4; r++) oacc[m][j][r] = 0.f;
        lsum[m][0] = 0.f; lsum[m][1] = 0.f;
    }

    int mat = lane >> 3;
    int rA  = (mat & 1)*8 + (lane & 7);
    int kgA = mat >> 1;
    int ntB = mat >> 1;
    int kgB = mat & 1;
    int rB  = lane & 7;
    int kvrow = (lane & 7) + ((lane >> 3) & 1) * 8;
    int kvchk = (lane >> 4);

    uint32_t qfrag[2][4][4];           // [msub][s][reg], loaded once at t=0

    #pragma unroll 1
    for (int t = 0; t < 16; t++){
        uint32_t kb = sb + ((t & 1) ? AK1 : AK0);
        uint32_t vb = sb + ((t & 1) ? AV1 : AV0);
        CP_WAIT0();
        __syncthreads();               // also protects buffers from next issue

        if (t == 0){
            #pragma unroll
            for (int m = 0; m < 2; m++)
                #pragma unroll
                for (int s = 0; s < 4; s++){
                    uint32_t off = (uint32_t)((wm + m*16 + rA)*128 + s*32 + kgA*16);
                    ldm4(sb + AQ + swz128(off), qfrag[m][s]);
                }
            __syncthreads();           // qfrag read before K1 overwrite below
        }
        if (t + 1 < 16)
            attn_issue_tile(sb, (t+1)&1, Kh, Vs, (t+1)*128, tid);

        // process key-tile in two 64-key halves to bound live registers
        #pragma unroll
        for (int half = 0; half < 2; half++){
            // ---- S = Q @ K^T : m32 x n64, k=64, fp16 accumulators ----
            uint32_t sacc2[2][16];
            #pragma unroll
            for (int m = 0; m < 2; m++)
                #pragma unroll
                for (int j = 0; j < 16; j++) sacc2[m][j] = 0u;
            #pragma unroll
            for (int s = 0; s < 4; s++){
                #pragma unroll
                for (int p = 0; p < 4; p++){
                    uint32_t bk[4];
                    uint32_t off = (uint32_t)(((half*4 + p)*16 + ntB*8 + rB)*128
                                              + s*32 + kgB*16);
                    ldm4(kb + swz128(off), bk);
                    #pragma unroll
                    for (int m = 0; m < 2; m++){
                        mma_f16a(&sacc2[m][4*p],   qfrag[m][s], &bk[0]);
                        mma_f16a(&sacc2[m][4*p+2], qfrag[m][s], &bk[2]);
                    }
                }
            }

            // ---- P = 2^S in place ----
            #pragma unroll
            for (int m = 0; m < 2; m++)
                #pragma unroll
                for (int j = 0; j < 16; j++) sacc2[m][j] = ex2_h2(sacc2[m][j]);

            // ---- row sums via HADD2 trees + quad butterfly (no ones MMAs) --
            // even-index regs = row r, odd-index = row r+8
            #pragma unroll
            for (int m = 0; m < 2; m++){
                __half2 se = __halves2half2(__ushort_as_half(0), __ushort_as_half(0));
                __half2 so = se;
                #pragma unroll
                for (int j = 0; j < 16; j += 2){
                    se = __hadd2(se, *(__half2*)&sacc2[m][j]);
                    so = __hadd2(so, *(__half2*)&sacc2[m][j+1]);
                }
                float2 fe = __half22float2(se);
                float2 fo = __half22float2(so);
                float re = fe.x + fe.y;
                float ro = fo.x + fo.y;
                re += __shfl_xor_sync(0xffffffffu, re, 1);
                re += __shfl_xor_sync(0xffffffffu, re, 2);
                ro += __shfl_xor_sync(0xffffffffu, ro, 1);
                ro += __shfl_xor_sync(0xffffffffu, ro, 2);
                lsum[m][0] += re;
                lsum[m][1] += ro;
            }

            // ---- O += P @ V (64 keys): V via ldmatrix.trans ----
            #pragma unroll
            for (int ks = 0; ks < 4; ks++){
                int krow0 = half*64 + ks*16;
                #pragma unroll
                for (int p = 0; p < 4; p++){
                    uint32_t bv[4];
                    uint32_t off = (uint32_t)((krow0 + kvrow)*128 + (p*2 + kvchk)*16);
                    ldm4t(vb + swz128(off), bv);
                    #pragma unroll
                    for (int m = 0; m < 2; m++){
                        mma_f16(oacc[m][2*p],   &sacc2[m][4*ks], &bv[0]);
                        mma_f16(oacc[m][2*p+1], &sacc2[m][4*ks], &bv[2]);
                    }
                }
            }
        }
    }

    // ---- normalize by l and write ----
    #pragma unroll
    for (int m = 0; m < 2; m++){
        float inv0 = 1.0f / lsum[m][0], inv1 = 1.0f / lsum[m][1];
        int r0 = qbase + wm + m*16 + (lane >> 2);
        size_t base0 = ((size_t)(b*SEQ) + r0)*DIM     + h*HDIM + (lane&3)*2;
        size_t base1 = ((size_t)(b*SEQ) + r0 + 8)*DIM + h*HDIM + (lane&3)*2;
        #pragma unroll
        for (int f = 0; f < 8; f++){
            *(__half2*)(g_aoh + base0 + f*8) =
                __halves2half2(__float2half_rn(oacc[m][f][0]*inv0),
                               __float2half_rn(oacc[m][f][1]*inv0));
            *(__half2*)(g_aoh + base1 + f*8) =
                __halves2half2(__float2half_rn(oacc[m][f][2]*inv1),
                               __float2half_rn(oacc[m][f][3]*inv1));
        }
    }
}

// ---------------- launch -----------------------------------------------------
extern "C" void kernel_launch(void* const* d_in, const int* in_sizes, int n_in,
                              void* d_out, int out_size){
    const float* x     = (const float*)d_in[0];
    const float* w_qkv = (const float*)d_in[1];
    const float* w_out = (const float*)d_in[2];
    const float* b_out = (const float*)d_in[3];
    float* out = (float*)d_out;

    cudaFuncSetAttribute(gemm_qkv_tc, cudaFuncAttributeMaxDynamicSharedMemorySize, GEMM_SMEM);
    cudaFuncSetAttribute(gemm_out_tc, cudaFuncAttributeMaxDynamicSharedMemorySize, GEMM_SMEM);
    cudaFuncSetAttribute(attn_tc,     cudaFuncAttributeMaxDynamicSharedMemorySize, ATT_SMEM);

    dim3 tb(32, 8);
    conv_x_k<<<MROWS*DIM/4/256, 256>>>(x);
    tr_w_k<<<dim3((QKVN+DIM)/32, DIM/32), tb>>>(w_qkv, w_out);

    gemm_qkv_tc<<<dim3(QKVN/128, MROWS/128), 128, GEMM_SMEM>>>();

    attn_tc<<<dim3(SEQ/128, HEADS, BATCH), 128, ATT_SMEM>>>();

    gemm_out_tc<<<dim3(DIM/128, MROWS/128), 128, GEMM_SMEM>>>(b_out, out);
}

// round 17
// speedup vs baseline: 1.1570x; 1.0297x over previous
#include <cuda_runtime.h>
#include <cuda_fp16.h>
#include <cstdint>

#define BATCH 2
#define SEQ   2048
#define DIM   1024
#define HEADS 16
#define HDIM  64
#define MROWS (BATCH*SEQ)          // 4096
#define QKVN  (3*DIM)              // 3072
#define QSCL  (0.03125f * 1.44269504088896f)   // DIM^-0.5 * log2e (use ex2)

// ---------------- scratch (device globals; no allocation allowed) ----------
__device__ __half g_xh[MROWS*DIM];                 // x hi
__device__ __half g_wqkvTh[QKVN*DIM];              // [n][k] hi
__device__ __half g_woutTh[DIM*DIM];               // [n][k] hi
__device__ __half g_qh[BATCH*HEADS*SEQ*HDIM];      // q hi (pre-scaled)
__device__ __half g_kh[BATCH*HEADS*SEQ*HDIM];      // k hi
__device__ __half g_vh[BATCH*HEADS*SEQ*HDIM];      // v hi [bh][s][d]
__device__ __half g_aoh[MROWS*DIM];                // attn out hi

// ---------------- helpers ----------------------------------------------------
__device__ __forceinline__ uint32_t smem_u32(const void* p){
    uint32_t a;
    asm("{ .reg .u64 t; cvta.to.shared.u64 t, %1; cvt.u32.u64 %0, t; }"
        : "=r"(a) : "l"(p));
    return a;
}
__device__ __forceinline__ uint32_t swz128(uint32_t o){ return o ^ ((o>>3)&0x70u); }

__device__ __forceinline__ void cp16(uint32_t saddr, const void* gaddr){
    asm volatile("cp.async.cg.shared.global [%0], [%1], 16;" :: "r"(saddr), "l"(gaddr));
}
#define CP_COMMIT() asm volatile("cp.async.commit_group;" ::: "memory")
#define CP_WAIT0()  asm volatile("cp.async.wait_group 0;"  ::: "memory")
#define CP_WAIT1()  asm volatile("cp.async.wait_group 1;"  ::: "memory")

__device__ __forceinline__ void ldm4(uint32_t addr, uint32_t r[4]){
    asm volatile("ldmatrix.sync.aligned.m8n8.x4.shared.b16 {%0,%1,%2,%3}, [%4];"
                 : "=r"(r[0]),"=r"(r[1]),"=r"(r[2]),"=r"(r[3]) : "r"(addr));
}
__device__ __forceinline__ void ldm4t(uint32_t addr, uint32_t r[4]){
    asm volatile("ldmatrix.sync.aligned.m8n8.x4.trans.shared.b16 {%0,%1,%2,%3}, [%4];"
                 : "=r"(r[0]),"=r"(r[1]),"=r"(r[2]),"=r"(r[3]) : "r"(addr));
}
__device__ __forceinline__ void mma_f16(float d[4], const uint32_t a[4], const uint32_t b[2]){
    asm volatile("mma.sync.aligned.m16n8k16.row.col.f32.f16.f16.f32 "
        "{%0,%1,%2,%3}, {%4,%5,%6,%7}, {%8,%9}, {%0,%1,%2,%3};"
        : "+f"(d[0]),"+f"(d[1]),"+f"(d[2]),"+f"(d[3])
        : "r"(a[0]),"r"(a[1]),"r"(a[2]),"r"(a[3]), "r"(b[0]),"r"(b[1]));
}
// fp16-accumulated mma (S-GEMM only; result feeds ex2 directly)
__device__ __forceinline__ void mma_f16a(uint32_t d[2], const uint32_t a[4], const uint32_t b[2]){
    asm volatile("mma.sync.aligned.m16n8k16.row.col.f16.f16.f16.f16 "
        "{%0,%1}, {%2,%3,%4,%5}, {%6,%7}, {%0,%1};"
        : "+r"(d[0]),"+r"(d[1])
        : "r"(a[0]),"r"(a[1]),"r"(a[2]),"r"(a[3]), "r"(b[0]),"r"(b[1]));
}
__device__ __forceinline__ uint32_t ex2_h2(uint32_t x){
    uint32_t r;
    asm("ex2.approx.f16x2 %0, %1;" : "=r"(r) : "r"(x));
    return r;
}

// ---------------- prep ---------------------------------------------------------
__global__ void conv_x_k(const float* __restrict__ in){
    int i = blockIdx.x*256 + threadIdx.x;           // float4 index
    float4 v = ((const float4*)in)[i];
    __half2* H = (__half2*)g_xh;
    H[2*i]   = __halves2half2(__float2half_rn(v.x), __float2half_rn(v.y));
    H[2*i+1] = __halves2half2(__float2half_rn(v.z), __float2half_rn(v.w));
}

// fused weight transposes: blocks x<96 -> w_qkv, else -> w_out
__global__ void tr_w_k(const float* __restrict__ wqkv, const float* __restrict__ wout){
    __shared__ float t[32][33];
    int bx = blockIdx.x;
    const float* in; __half* oh; int cols, c0;
    if (bx < QKVN/32){ in = wqkv; oh = g_wqkvTh; cols = QKVN; c0 = bx*32; }
    else             { in = wout; oh = g_woutTh; cols = DIM;  c0 = (bx - QKVN/32)*32; }
    int r0 = blockIdx.y * 32;
    int x = threadIdx.x, y = threadIdx.y;
    #pragma unroll
    for (int i = 0; i < 32; i += 8) t[y+i][x] = in[(size_t)(r0+y+i)*cols + c0+x];
    __syncthreads();
    #pragma unroll
    for (int i = 0; i < 32; i += 8)
        oh[(size_t)(c0+y+i)*DIM + r0+x] = __float2half_rn(t[x][y+i]);
}

// ---------------- fp16 mma GEMM core: 4 warps, 64x64 warp tile (R13) -----------
#define KC 64
#define NCHUNK (DIM/KC)
#define GBUF 32768u                 // 16K A + 16K B per buffer
#define GEMM_SMEM (3*GBUF)

__device__ __forceinline__ void g_issue(uint32_t sb, int buf,
        const __half* __restrict__ Ah, const __half* __restrict__ Bh,
        int c, int tid){
    uint32_t base = sb + (uint32_t)buf * GBUF;
    #pragma unroll
    for (int i = 0; i < 8; i++){
        int idx = tid + i*128;
        int row = idx >> 3, g = idx & 7;
        uint32_t off = swz128((uint32_t)(row*128 + g*16));
        cp16(base + off,          Ah + (size_t)row*DIM + c*KC + g*8);
        cp16(base + 16384u + off, Bh + (size_t)row*DIM + c*KC + g*8);
    }
    CP_COMMIT();
}

__device__ __forceinline__ void g_compute(uint32_t sb, int buf,
        int wm, int wn, int lane, float acc[4][8][4]){
    uint32_t abase = sb + (uint32_t)buf * GBUF;
    uint32_t bbase = abase + 16384u;
    int mat = lane >> 3;
    int rA  = (mat & 1)*8 + (lane & 7);
    int kgA = mat >> 1;
    int ntB = mat >> 1;
    int kgB = mat & 1;
    int rB  = lane & 7;
    #pragma unroll
    for (int s = 0; s < 4; s++){
        uint32_t ah[4][4];
        #pragma unroll
        for (int mi = 0; mi < 4; mi++){
            uint32_t off = (uint32_t)((wm + mi*16 + rA)*128 + s*32 + kgA*16);
            ldm4(abase + swz128(off), ah[mi]);
        }
        uint32_t bh[4][4];
        #pragma unroll
        for (int p = 0; p < 4; p++){
            uint32_t off = (uint32_t)((wn + p*16 + ntB*8 + rB)*128 + s*32 + kgB*16);
            ldm4(bbase + swz128(off), bh[p]);
        }
        #pragma unroll
        for (int mi = 0; mi < 4; mi++)
            #pragma unroll
            for (int nj = 0; nj < 8; nj++)
                mma_f16(acc[mi][nj], ah[mi], &bh[nj>>1][(nj&1)*2]);
    }
}

__device__ __forceinline__ void gemm_main(uint32_t sb,
        const __half* Ah, const __half* Bh,
        int tid, int wm, int wn, int lane, float acc[4][8][4]){
    g_issue(sb, 0, Ah, Bh, 0, tid);
    g_issue(sb, 1, Ah, Bh, 1, tid);
    int bc = 0, bn2 = 2;            // rotating buffer indices: c%3, (c+2)%3
    #pragma unroll 1
    for (int c = 0; c < NCHUNK; c++){
        if (c + 1 < NCHUNK) CP_WAIT1(); else CP_WAIT0();
        __syncthreads();
        if (c + 2 < NCHUNK)
            g_issue(sb, bn2, Ah, Bh, c+2, tid);
        g_compute(sb, bc, wm, wn, lane, acc);
        if (++bc == 3) bc = 0;
        if (++bn2 == 3) bn2 = 0;
    }
}

__global__ void __launch_bounds__(128,2) gemm_qkv_tc(){
    extern __shared__ char smem[];
    uint32_t sb = smem_u32(smem);
    int tid = threadIdx.x, lane = tid & 31, wid = tid >> 5;
    int wm = (wid & 1)*64, wn = (wid >> 1)*64;
    int bm = blockIdx.y*128, bn = blockIdx.x*128;

    float acc[4][8][4];
    #pragma unroll
    for (int i=0;i<4;i++) for(int j=0;j<8;j++) for(int r=0;r<4;r++) acc[i][j][r]=0.f;

    gemm_main(sb, g_xh + (size_t)bm*DIM, g_wqkvTh + (size_t)bn*DIM,
              tid, wm, wn, lane, acc);

    // epilogue: scatter into q (pre-scaled), k, v — all fp16 hi
    int cb = bn + wn;                 // 64-aligned
    int part = cb >> 10;
    int h = (cb & (DIM-1)) >> 6;
    __half* dstp = (part==0 ? g_qh : (part==1 ? g_kh : g_vh));
    float scl = (part==0) ? QSCL : 1.0f;
    #pragma unroll
    for (int mi = 0; mi < 4; mi++){
        #pragma unroll
        for (int hi2 = 0; hi2 < 2; hi2++){
            int m = bm + wm + mi*16 + hi2*8 + (lane>>2);
            int b = m >> 11, n = m & (SEQ-1);
            size_t base = ((size_t)(b*HEADS + h)*SEQ + n)*HDIM + (lane&3)*2;
            #pragma unroll
            for (int nj = 0; nj < 8; nj++){
                float v0 = acc[mi][nj][hi2*2]*scl, v1 = acc[mi][nj][hi2*2+1]*scl;
                *(__half2*)(dstp + base + nj*8) =
                    __halves2half2(__float2half_rn(v0), __float2half_rn(v1));
            }
        }
    }
}

__global__ void __launch_bounds__(128,2) gemm_out_tc(const float* __restrict__ bias,
                                                     float* __restrict__ Out){
    extern __shared__ char smem[];
    uint32_t sb = smem_u32(smem);
    int tid = threadIdx.x, lane = tid & 31, wid = tid >> 5;
    int wm = (wid & 1)*64, wn = (wid >> 1)*64;
    int bm = blockIdx.y*128, bn = blockIdx.x*128;

    float acc[4][8][4];
    #pragma unroll
    for (int i=0;i<4;i++) for(int j=0;j<8;j++) for(int r=0;r<4;r++) acc[i][j][r]=0.f;

    gemm_main(sb, g_aoh + (size_t)bm*DIM, g_woutTh + (size_t)bn*DIM,
              tid, wm, wn, lane, acc);

    #pragma unroll
    for (int mi = 0; mi < 4; mi++){
        #pragma unroll
        for (int hi2 = 0; hi2 < 2; hi2++){
            int m = bm + wm + mi*16 + hi2*8 + (lane>>2);
            float* dst = Out + (size_t)m*DIM + bn + wn + (lane&3)*2;
            #pragma unroll
            for (int nj = 0; nj < 8; nj++){
                int c = bn + wn + nj*8 + (lane&3)*2;
                float2 v = make_float2(acc[mi][nj][hi2*2]   + bias[c],
                                       acc[mi][nj][hi2*2+1] + bias[c+1]);
                *(float2*)(dst + nj*8) = v;
            }
        }
    }
}

// ---------------- flash attention: R13 (m32 warps, Q in K1, ones column) -------
#define AK0 0u
#define AK1 16384u
#define AQ  AK1
#define AV0 32768u
#define AV1 49152u
#define ATT_SMEM (AV1 + 16384u)     // 64K

__device__ __forceinline__ void attn_issue_tile(uint32_t sb, int buf,
        const __half* __restrict__ Kh, const __half* __restrict__ Vs,
        int t0, int tid){
    uint32_t kb = sb + (buf ? AK1 : AK0);
    uint32_t vb = sb + (buf ? AV1 : AV0);
    #pragma unroll
    for (int i = 0; i < 8; i++){
        int idx = tid + i*128;
        int row = idx >> 3, g = idx & 7;
        uint32_t off = swz128((uint32_t)(row*128 + g*16));
        cp16(kb + off, Kh + (size_t)(t0+row)*HDIM + g*8);
        cp16(vb + off, Vs + (size_t)(t0+row)*HDIM + g*8);
    }
    CP_COMMIT();
}

__global__ void __launch_bounds__(128,3) attn_tc(){
    extern __shared__ char smem[];
    uint32_t sb = smem_u32(smem);
    int tid = threadIdx.x, lane = tid & 31, wid = tid >> 5;
    int wm = wid * 32;                 // 4 warps x 32 rows = 128
    int b = blockIdx.z, h = blockIdx.y, bh = b*HEADS + h;
    int qbase = blockIdx.x * 128;

    const __half* Qh = g_qh + ((size_t)bh*SEQ + qbase)*HDIM;
    const __half* Kh = g_kh + (size_t)bh*SEQ*HDIM;
    const __half* Vs = g_vh + (size_t)bh*SEQ*HDIM;

    // Q tile into AQ (= K1 buffer) — own cp.async group, consumed at t=0 only
    #pragma unroll
    for (int i = 0; i < 8; i++){
        int idx = tid + i*128;
        int row = idx >> 3, g = idx & 7;
        cp16(sb + AQ + swz128((uint32_t)(row*128 + g*16)),
             Qh + (size_t)row*HDIM + g*8);
    }
    CP_COMMIT();

    attn_issue_tile(sb, 0, Kh, Vs, 0, tid);

    float oacc[2][8][4];               // [msub][n-frag][reg], d 0..63
    float oaccl[2][4];                 // [msub][reg], ones column (row sums)
    #pragma unroll
    for (int m = 0; m < 2; m++){
        #pragma unroll
        for (int j = 0; j < 8; j++)
            #pragma unroll
            for (int r = 0; r < 4; r++) oacc[m][j][r] = 0.f;
        #pragma unroll
        for (int r = 0; r < 4; r++) oaccl[m][r] = 0.f;
    }

    int mat = lane >> 3;
    int rA  = (mat & 1)*8 + (lane & 7);
    int kgA = mat >> 1;
    int ntB = mat >> 1;
    int kgB = mat & 1;
    int rB  = lane & 7;
    int kvrow = (lane & 7) + ((lane >> 3) & 1) * 8;
    int kvchk = (lane >> 4);
    uint32_t bvc = ((lane >> 2) == 0) ? 0x3C003C00u : 0u;
    uint32_t bvc2[2] = { bvc, bvc };

    uint32_t qfrag[2][4][4];           // [msub][s][reg], loaded once at t=0

    #pragma unroll 1
    for (int t = 0; t < 16; t++){
        uint32_t kb = sb + ((t & 1) ? AK1 : AK0);
        uint32_t vb = sb + ((t & 1) ? AV1 : AV0);
        CP_WAIT0();
        __syncthreads();               // also protects buffers from next issue

        if (t == 0){
            #pragma unroll
            for (int m = 0; m < 2; m++)
                #pragma unroll
                for (int s = 0; s < 4; s++){
                    uint32_t off = (uint32_t)((wm + m*16 + rA)*128 + s*32 + kgA*16);
                    ldm4(sb + AQ + swz128(off), qfrag[m][s]);
                }
            __syncthreads();           // qfrag read before K1 overwrite below
        }
        if (t + 1 < 16)
            attn_issue_tile(sb, (t+1)&1, Kh, Vs, (t+1)*128, tid);

        // process key-tile in two 64-key halves to bound live registers
        #pragma unroll
        for (int half = 0; half < 2; half++){
            // ---- S = Q @ K^T : m32 x n64, k=64, fp16 accumulators ----
            uint32_t sacc2[2][16];
            #pragma unroll
            for (int m = 0; m < 2; m++)
                #pragma unroll
                for (int j = 0; j < 16; j++) sacc2[m][j] = 0u;
            #pragma unroll
            for (int s = 0; s < 4; s++){
                #pragma unroll
                for (int p = 0; p < 4; p++){
                    uint32_t bk[4];
                    uint32_t off = (uint32_t)(((half*4 + p)*16 + ntB*8 + rB)*128
                                              + s*32 + kgB*16);
                    ldm4(kb + swz128(off), bk);
                    #pragma unroll
                    for (int m = 0; m < 2; m++){
                        mma_f16a(&sacc2[m][4*p],   qfrag[m][s], &bk[0]);
                        mma_f16a(&sacc2[m][4*p+2], qfrag[m][s], &bk[2]);
                    }
                }
            }

            // ---- P = 2^S in place ----
            #pragma unroll
            for (int m = 0; m < 2; m++)
                #pragma unroll
                for (int j = 0; j < 16; j++) sacc2[m][j] = ex2_h2(sacc2[m][j]);

            // ---- O += P @ V (64 keys): V via ldmatrix.trans; ones via const --
            #pragma unroll
            for (int ks = 0; ks < 4; ks++){
                int krow0 = half*64 + ks*16;
                #pragma unroll
                for (int p = 0; p < 4; p++){
                    uint32_t bv[4];
                    uint32_t off = (uint32_t)((krow0 + kvrow)*128 + (p*2 + kvchk)*16);
                    ldm4t(vb + swz128(off), bv);
                    #pragma unroll
                    for (int m = 0; m < 2; m++){
                        mma_f16(oacc[m][2*p],   &sacc2[m][4*ks], &bv[0]);
                        mma_f16(oacc[m][2*p+1], &sacc2[m][4*ks], &bv[2]);
                    }
                }
                #pragma unroll
                for (int m = 0; m < 2; m++)
                    mma_f16(oaccl[m], &sacc2[m][4*ks], bvc2);
            }
        }
    }

    // ---- normalize by l (ones fragment col 0) and write ----
    #pragma unroll
    for (int m = 0; m < 2; m++){
        float l0 = __shfl_sync(0xffffffffu, oaccl[m][0], lane & ~3);
        float l1 = __shfl_sync(0xffffffffu, oaccl[m][2], lane & ~3);
        float inv0 = 1.0f / l0, inv1 = 1.0f / l1;
        int r0 = qbase + wm + m*16 + (lane >> 2);
        size_t base0 = ((size_t)(b*SEQ) + r0)*DIM     + h*HDIM + (lane&3)*2;
        size_t base1 = ((size_t)(b*SEQ) + r0 + 8)*DIM + h*HDIM + (lane&3)*2;
        #pragma unroll
        for (int f = 0; f < 8; f++){
            *(__half2*)(g_aoh + base0 + f*8) =
                __halves2half2(__float2half_rn(oacc[m][f][0]*inv0),
                               __float2half_rn(oacc[m][f][1]*inv0));
            *(__half2*)(g_aoh + base1 + f*8) =
                __halves2half2(__float2half_rn(oacc[m][f][2]*inv1),
                               __float2half_rn(oacc[m][f][3]*inv1));
        }
    }
}

// ---------------- launch -----------------------------------------------------
extern "C" void kernel_launch(void* const* d_in, const int* in_sizes, int n_in,
                              void* d_out, int out_size){
    const float* x     = (const float*)d_in[0];
    const float* w_qkv = (const float*)d_in[1];
    const float* w_out = (const float*)d_in[2];
    const float* b_out = (const float*)d_in[3];
    float* out = (float*)d_out;

    cudaFuncSetAttribute(gemm_qkv_tc, cudaFuncAttributeMaxDynamicSharedMemorySize, GEMM_SMEM);
    cudaFuncSetAttribute(gemm_out_tc, cudaFuncAttributeMaxDynamicSharedMemorySize, GEMM_SMEM);
    cudaFuncSetAttribute(attn_tc,     cudaFuncAttributeMaxDynamicSharedMemorySize, ATT_SMEM);

    dim3 tb(32, 8);
    conv_x_k<<<MROWS*DIM/4/256, 256>>>(x);
    tr_w_k<<<dim3((QKVN+DIM)/32, DIM/32), tb>>>(w_qkv, w_out);

    gemm_qkv_tc<<<dim3(QKVN/128, MROWS/128), 128, GEMM_SMEM>>>();

    attn_tc<<<dim3(SEQ/128, HEADS, BATCH), 128, ATT_SMEM>>>();

    gemm_out_tc<<<dim3(DIM/128, MROWS/128), 128, GEMM_SMEM>>>(b_out, out);
}